// round 2
// baseline (speedup 1.0000x reference)
#include <cuda_runtime.h>
#include <cstdint>

#define HIDDEN    1024
#define HEADS     16
#define HEAD_DIM  64
#define BATCH     4
#define SEQ       1024
#define ROWS      (BATCH*SEQ)        // 4096
#define BETA_F    0.9f
#define CLAMP_F   1.0f
#define STATE_CAP_F 10.0f

// ---------------- scratch (static device allocations are allowed) ----------
__device__ float g_q[ROWS*HIDDEN];
__device__ float g_k[ROWS*HIDDEN];
__device__ float g_v[ROWS*HIDDEN];
__device__ float g_o[ROWS*HIDDEN];
__device__ float g_state_scratch[BATCH*HEADS*HEAD_DIM*HEAD_DIM];

// ---------------------------------------------------------------------------
// GEMM: C[m,n] = sum_k A[m,k]*B[n,k] + bias[n]   (A:[M,K], B:[N,K] row-major)
// BM=BN=128, BK=8, 256 threads, 8x8 microtile.
// ---------------------------------------------------------------------------
__device__ __forceinline__ void gemm_nt_body(
    const float* __restrict__ A, const float* __restrict__ B,
    const float* __restrict__ bias, float* __restrict__ C,
    int M, int N, int K, int m0, int n0)
{
    __shared__ float As[8][128];
    __shared__ float Bs[8][128];

    const int tid  = threadIdx.x;
    const int tx   = tid & 15;        // 0..15 -> n microtile
    const int ty   = tid >> 4;        // 0..15 -> m microtile
    const int lrow = tid >> 1;        // 0..127
    const int lcol = (tid & 1) * 4;   // 0 or 4

    const float* Aptr = A + (size_t)(m0 + lrow) * K + lcol;
    const float* Bptr = B + (size_t)(n0 + lrow) * K + lcol;

    float acc[8][8];
#pragma unroll
    for (int i = 0; i < 8; i++)
#pragma unroll
        for (int j = 0; j < 8; j++) acc[i][j] = 0.f;

    for (int k0 = 0; k0 < K; k0 += 8) {
        float4 a4 = *(const float4*)(Aptr + k0);
        float4 b4 = *(const float4*)(Bptr + k0);
        __syncthreads();
        As[lcol+0][lrow] = a4.x; As[lcol+1][lrow] = a4.y;
        As[lcol+2][lrow] = a4.z; As[lcol+3][lrow] = a4.w;
        Bs[lcol+0][lrow] = b4.x; Bs[lcol+1][lrow] = b4.y;
        Bs[lcol+2][lrow] = b4.z; Bs[lcol+3][lrow] = b4.w;
        __syncthreads();
#pragma unroll
        for (int kk = 0; kk < 8; kk++) {
            float af[8], bf[8];
            *(float4*)(af)     = *(const float4*)&As[kk][ty*8];
            *(float4*)(af + 4) = *(const float4*)&As[kk][ty*8 + 4];
            *(float4*)(bf)     = *(const float4*)&Bs[kk][tx*8];
            *(float4*)(bf + 4) = *(const float4*)&Bs[kk][tx*8 + 4];
#pragma unroll
            for (int i = 0; i < 8; i++)
#pragma unroll
                for (int j = 0; j < 8; j++)
                    acc[i][j] += af[i] * bf[j];
        }
    }

    float bv[8];
#pragma unroll
    for (int j = 0; j < 8; j++) bv[j] = bias[n0 + tx*8 + j];

#pragma unroll
    for (int i = 0; i < 8; i++) {
        float* cp = C + (size_t)(m0 + ty*8 + i) * N + n0 + tx*8;
#pragma unroll
        for (int j = 0; j < 8; j++) cp[j] = acc[i][j] + bv[j];
    }
}

__global__ __launch_bounds__(256) void gemm_nt_kernel(
    const float* __restrict__ A, const float* __restrict__ B,
    const float* __restrict__ bias, float* __restrict__ C,
    int M, int N, int K)
{
    gemm_nt_body(A, B, bias, C, M, N, K, blockIdx.y * 128, blockIdx.x * 128);
}

// One launch computes q, k, v (blockIdx.z selects the weight/output).
__global__ __launch_bounds__(256) void gemm_qkv_kernel(
    const float* __restrict__ X,
    const float* __restrict__ Wq, const float* __restrict__ bq,
    const float* __restrict__ Wk, const float* __restrict__ bk,
    const float* __restrict__ Wv, const float* __restrict__ bv)
{
    const float* W; const float* bias; float* out;
    if (blockIdx.z == 0)      { W = Wq; bias = bq; out = g_q; }
    else if (blockIdx.z == 1) { W = Wk; bias = bk; out = g_k; }
    else                      { W = Wv; bias = bv; out = g_v; }
    gemm_nt_body(X, W, bias, out, ROWS, HIDDEN, HIDDEN,
                 blockIdx.y * 128, blockIdx.x * 128);
}

// ---------------------------------------------------------------------------
// L2 normalize q and k per head vector (64 contiguous floats).
// One warp per vector; lane handles 2 elements.
// Total vectors: 2 * ROWS * HEADS = 131072 -> 16384 blocks of 8 warps.
// ---------------------------------------------------------------------------
__global__ __launch_bounds__(256) void l2norm_kernel()
{
    const int warp = threadIdx.x >> 5;
    const int lane = threadIdx.x & 31;
    const long vid = (long)blockIdx.x * 8 + warp;   // 0 .. 131071
    const long NV  = (long)ROWS * HEADS;            // 65536
    float* base = (vid < NV) ? g_q : g_k;
    const long v = vid & (NV - 1);
    float* p = base + v * HEAD_DIM + lane * 2;
    float2 x = *(float2*)p;
    float ss = x.x * x.x + x.y * x.y;
#pragma unroll
    for (int off = 16; off; off >>= 1)
        ss += __shfl_xor_sync(0xffffffffu, ss, off);
    float n   = sqrtf(ss);
    float inv = 1.0f / fmaxf(n, 1e-12f);
    x.x *= inv; x.y *= inv;
    *(float2*)p = x;
}

// ---------------------------------------------------------------------------
// Sequential delta-rule scan. One 64-thread block per (b,h).
// Thread t owns state column t in registers (S[d][t], d=0..63) and mirrors
// it to shared (padded) so the o-phase can read rows conflict-free.
// ---------------------------------------------------------------------------
__device__ __forceinline__ float clip1(float x) {
    return fminf(fmaxf(x, -CLAMP_F), CLAMP_F);
}

__global__ __launch_bounds__(64) void scan_kernel(float* __restrict__ state_out)
{
    __shared__ float Ssh[HEAD_DIM][HEAD_DIM + 1];
    __shared__ float ksh[HEAD_DIM];
    __shared__ float qsh[HEAD_DIM];
    __shared__ float wmax[2];

    const int t  = threadIdx.x;          // column index / element index
    const int bh = blockIdx.x;           // 0..63
    const int b  = bh >> 4;
    const int h  = bh & 15;

    float Scol[HEAD_DIM];
#pragma unroll
    for (int d = 0; d < HEAD_DIM; d++) { Scol[d] = 0.f; Ssh[d][t] = 0.f; }
    __syncthreads();

    const size_t base = (size_t)b * SEQ * HIDDEN + (size_t)h * HEAD_DIM + t;

    // prefetch step 0
    float kv_n = g_k[base];
    float vv_n = g_v[base];
    float qv_n = g_q[base];

    for (int s = 0; s < SEQ; s++) {
        const size_t idx = base + (size_t)s * HIDDEN;
        const float kv = kv_n, vv = vv_n, qv = qv_n;
        ksh[t] = kv; qsh[t] = qv;
        __syncthreads();

        // prefetch next step (overlaps the whole step's compute)
        if (s + 1 < SEQ) {
            const size_t nidx = idx + HIDDEN;
            kv_n = g_k[nidx]; vv_n = g_v[nidx]; qv_n = g_q[nidx];
        }

        // v_old[t] = sum_d k[d] * S[d][t]
        float a0 = 0.f, a1 = 0.f, a2 = 0.f, a3 = 0.f;
#pragma unroll
        for (int d = 0; d < HEAD_DIM; d += 4) {
            a0 += ksh[d+0] * Scol[d+0];
            a1 += ksh[d+1] * Scol[d+1];
            a2 += ksh[d+2] * Scol[d+2];
            a3 += ksh[d+3] * Scol[d+3];
        }
        const float vold  = (a0 + a1) + (a2 + a3);
        const float delta = clip1(vv - vold);
        const float bd    = BETA_F * delta;

        // S[d][t] += clip(beta * k[d] * delta[t]); track max|S|
        float lmax = 0.f;
#pragma unroll
        for (int d = 0; d < HEAD_DIM; d++) {
            float sdt = Scol[d] + clip1(bd * ksh[d]);
            Scol[d] = sdt;
            lmax = fmaxf(lmax, fabsf(sdt));
        }
        // reduce max across 64 threads (2 warps)
#pragma unroll
        for (int off = 16; off; off >>= 1)
            lmax = fmaxf(lmax, __shfl_xor_sync(0xffffffffu, lmax, off));
        if ((t & 31) == 0) wmax[t >> 5] = lmax;
        __syncthreads();
        const float gmax  = fmaxf(wmax[0], wmax[1]);
        const float scale = (gmax > STATE_CAP_F) ? 0.9f : 1.0f;

        // scale and publish to shared for row reads
#pragma unroll
        for (int d = 0; d < HEAD_DIM; d++) {
            float sdt = Scol[d] * scale;
            Scol[d] = sdt;
            Ssh[d][t] = sdt;
        }
        __syncthreads();

        // o[t] = clip(sum_j S[t][j] * q[j])
        float o0 = 0.f, o1 = 0.f, o2 = 0.f, o3 = 0.f;
#pragma unroll
        for (int j = 0; j < HEAD_DIM; j += 4) {
            o0 += Ssh[t][j+0] * qsh[j+0];
            o1 += Ssh[t][j+1] * qsh[j+1];
            o2 += Ssh[t][j+2] * qsh[j+2];
            o3 += Ssh[t][j+3] * qsh[j+3];
        }
        g_o[idx] = clip1((o0 + o1) + (o2 + o3));
        __syncthreads();   // protect ksh/qsh/Ssh for next iteration
    }

    // final state: state_out[b][h][d][e], thread t writes column e = t
    float* sp = state_out + (size_t)bh * HEAD_DIM * HEAD_DIM;
#pragma unroll
    for (int d = 0; d < HEAD_DIM; d++)
        sp[d * HEAD_DIM + t] = Scol[d];
}

// ---------------------------------------------------------------------------
extern "C" void kernel_launch(void* const* d_in, const int* in_sizes, int n_in,
                              void* d_out, int out_size)
{
    (void)in_sizes; (void)n_in;
    const float* x  = (const float*)d_in[0];
    const float* Wq = (const float*)d_in[1];
    const float* bq = (const float*)d_in[2];
    const float* Wk = (const float*)d_in[3];
    const float* bk = (const float*)d_in[4];
    const float* Wv = (const float*)d_in[5];
    const float* bv = (const float*)d_in[6];
    const float* Wo = (const float*)d_in[7];
    const float* bo = (const float*)d_in[8];

    float* o_ptr = nullptr;
    cudaGetSymbolAddress((void**)&o_ptr, g_o);

    const int OUT_ELEMS   = ROWS * HIDDEN;                         // 4194304
    const int STATE_ELEMS = BATCH * HEADS * HEAD_DIM * HEAD_DIM;   // 262144

    float* state_out;
    if (out_size >= OUT_ELEMS + STATE_ELEMS) {
        state_out = (float*)d_out + OUT_ELEMS;
    } else {
        cudaGetSymbolAddress((void**)&state_out, g_state_scratch);
    }

    // 1) QKV projections (single launch, z selects tensor)
    dim3 gq(HIDDEN / 128, ROWS / 128, 3);
    gemm_qkv_kernel<<<gq, 256>>>(x, Wq, bq, Wk, bk, Wv, bv);

    // 2) L2 norm of q and k: 131072 head vectors, 1 warp each, 8 warps/block
    l2norm_kernel<<<(2 * ROWS * HEADS) / 8, 256>>>();

    // 3) sequential delta-rule scan, one block per (b,h)
    scan_kernel<<<BATCH * HEADS, 64>>>(state_out);

    // 4) output projection -> d_out
    dim3 go(HIDDEN / 128, ROWS / 128);
    gemm_nt_kernel<<<go, 256>>>(o_ptr, Wo, bo, (float*)d_out,
                                ROWS, HIDDEN, HIDDEN);
}

// round 3
// speedup vs baseline: 1.1346x; 1.1346x over previous
#include <cuda_runtime.h>
#include <cstdint>

#define HIDDEN    1024
#define HEADS     16
#define HEAD_DIM  64
#define BATCH     4
#define SEQ       1024
#define ROWS      (BATCH*SEQ)        // 4096
#define BETA_F    0.9f
#define CLAMP_F   1.0f
#define STATE_CAP_F 10.0f
#define BK        16

// ---------------- scratch (static device arrays are allowed) ---------------
__device__ float g_q[ROWS*HIDDEN];
__device__ float g_k[ROWS*HIDDEN];
__device__ float g_v[ROWS*HIDDEN];
__device__ float g_o[ROWS*HIDDEN];
__device__ float g_state_scratch[BATCH*HEADS*HEAD_DIM*HEAD_DIM];

// ---------------------------------------------------------------------------
// GEMM: C[m,n] = sum_k A[m,k]*B[n,k] + bias[n]   (A:[M,K], B:[N,K] row-major)
// BM=BN=128, BK=16, 256 threads, 8x8 microtile, double-buffered smem,
// one __syncthreads per K-iteration.
// ---------------------------------------------------------------------------
__device__ __forceinline__ void gemm_nt_body(
    const float* __restrict__ A, const float* __restrict__ B,
    const float* __restrict__ bias, float* __restrict__ C,
    int N, int K, int m0, int n0)
{
    __shared__ float As[2][BK][128];   // 16 KB
    __shared__ float Bs[2][BK][128];   // 16 KB

    const int tid  = threadIdx.x;
    const int tx   = tid & 15;        // n microtile
    const int ty   = tid >> 4;        // m microtile
    const int lrow = tid >> 1;        // 0..127
    const int lcol = (tid & 1) * 8;   // 0 or 8

    const float* Aptr = A + (size_t)(m0 + lrow) * K + lcol;
    const float* Bptr = B + (size_t)(n0 + lrow) * K + lcol;

    float acc[8][8];
#pragma unroll
    for (int i = 0; i < 8; i++)
#pragma unroll
        for (int j = 0; j < 8; j++) acc[i][j] = 0.f;

    // prologue: stage 0
    float4 a0 = *(const float4*)(Aptr);
    float4 a1 = *(const float4*)(Aptr + 4);
    float4 b0 = *(const float4*)(Bptr);
    float4 b1 = *(const float4*)(Bptr + 4);
    As[0][lcol+0][lrow]=a0.x; As[0][lcol+1][lrow]=a0.y; As[0][lcol+2][lrow]=a0.z; As[0][lcol+3][lrow]=a0.w;
    As[0][lcol+4][lrow]=a1.x; As[0][lcol+5][lrow]=a1.y; As[0][lcol+6][lrow]=a1.z; As[0][lcol+7][lrow]=a1.w;
    Bs[0][lcol+0][lrow]=b0.x; Bs[0][lcol+1][lrow]=b0.y; Bs[0][lcol+2][lrow]=b0.z; Bs[0][lcol+3][lrow]=b0.w;
    Bs[0][lcol+4][lrow]=b1.x; Bs[0][lcol+5][lrow]=b1.y; Bs[0][lcol+6][lrow]=b1.z; Bs[0][lcol+7][lrow]=b1.w;
    __syncthreads();

    int buf = 0;
    for (int k0 = 0; k0 < K; k0 += BK) {
        const bool has_next = (k0 + BK) < K;
        if (has_next) {
            a0 = *(const float4*)(Aptr + k0 + BK);
            a1 = *(const float4*)(Aptr + k0 + BK + 4);
            b0 = *(const float4*)(Bptr + k0 + BK);
            b1 = *(const float4*)(Bptr + k0 + BK + 4);
        }
#pragma unroll
        for (int kk = 0; kk < BK; kk++) {
            float af[8], bf[8];
            *(float4*)(af)     = *(const float4*)&As[buf][kk][ty*8];
            *(float4*)(af + 4) = *(const float4*)&As[buf][kk][ty*8 + 4];
            *(float4*)(bf)     = *(const float4*)&Bs[buf][kk][tx*8];
            *(float4*)(bf + 4) = *(const float4*)&Bs[buf][kk][tx*8 + 4];
#pragma unroll
            for (int i = 0; i < 8; i++)
#pragma unroll
                for (int j = 0; j < 8; j++)
                    acc[i][j] += af[i] * bf[j];
        }
        if (has_next) {
            const int nb = buf ^ 1;
            As[nb][lcol+0][lrow]=a0.x; As[nb][lcol+1][lrow]=a0.y; As[nb][lcol+2][lrow]=a0.z; As[nb][lcol+3][lrow]=a0.w;
            As[nb][lcol+4][lrow]=a1.x; As[nb][lcol+5][lrow]=a1.y; As[nb][lcol+6][lrow]=a1.z; As[nb][lcol+7][lrow]=a1.w;
            Bs[nb][lcol+0][lrow]=b0.x; Bs[nb][lcol+1][lrow]=b0.y; Bs[nb][lcol+2][lrow]=b0.z; Bs[nb][lcol+3][lrow]=b0.w;
            Bs[nb][lcol+4][lrow]=b1.x; Bs[nb][lcol+5][lrow]=b1.y; Bs[nb][lcol+6][lrow]=b1.z; Bs[nb][lcol+7][lrow]=b1.w;
            __syncthreads();
            buf = nb;
        }
    }

    float bv[8];
#pragma unroll
    for (int j = 0; j < 8; j++) bv[j] = bias[n0 + tx*8 + j];

#pragma unroll
    for (int i = 0; i < 8; i++) {
        float* cp = C + (size_t)(m0 + ty*8 + i) * N + n0 + tx*8;
        float4 c0, c1;
        c0.x = acc[i][0]+bv[0]; c0.y = acc[i][1]+bv[1];
        c0.z = acc[i][2]+bv[2]; c0.w = acc[i][3]+bv[3];
        c1.x = acc[i][4]+bv[4]; c1.y = acc[i][5]+bv[5];
        c1.z = acc[i][6]+bv[6]; c1.w = acc[i][7]+bv[7];
        *(float4*)(cp)     = c0;
        *(float4*)(cp + 4) = c1;
    }
}

__global__ __launch_bounds__(256) void gemm_nt_kernel(
    const float* __restrict__ A, const float* __restrict__ B,
    const float* __restrict__ bias, float* __restrict__ C,
    int N, int K)
{
    gemm_nt_body(A, B, bias, C, N, K, blockIdx.y * 128, blockIdx.x * 128);
}

// One launch computes q, k, v (blockIdx.z selects the weight/output).
__global__ __launch_bounds__(256) void gemm_qkv_kernel(
    const float* __restrict__ X,
    const float* __restrict__ Wq, const float* __restrict__ bq,
    const float* __restrict__ Wk, const float* __restrict__ bk,
    const float* __restrict__ Wv, const float* __restrict__ bv)
{
    const float* W; const float* bias; float* out;
    if (blockIdx.z == 0)      { W = Wq; bias = bq; out = g_q; }
    else if (blockIdx.z == 1) { W = Wk; bias = bk; out = g_k; }
    else                      { W = Wv; bias = bv; out = g_v; }
    gemm_nt_body(X, W, bias, out, HIDDEN, HIDDEN,
                 blockIdx.y * 128, blockIdx.x * 128);
}

// ---------------------------------------------------------------------------
// L2 normalize q and k per head vector (64 contiguous floats).
// One warp per vector, 131072 vectors total -> 16384 blocks of 8 warps.
// ---------------------------------------------------------------------------
__global__ __launch_bounds__(256) void l2norm_kernel()
{
    const int warp = threadIdx.x >> 5;
    const int lane = threadIdx.x & 31;
    const long vid = (long)blockIdx.x * 8 + warp;   // 0 .. 131071
    const long NV  = (long)ROWS * HEADS;            // 65536
    float* base = (vid < NV) ? g_q : g_k;
    const long v = vid & (NV - 1);
    float* p = base + v * HEAD_DIM + lane * 2;
    float2 x = *(float2*)p;
    float ss = x.x * x.x + x.y * x.y;
#pragma unroll
    for (int off = 16; off; off >>= 1)
        ss += __shfl_xor_sync(0xffffffffu, ss, off);
    float n   = sqrtf(ss);
    float inv = 1.0f / fmaxf(n, 1e-12f);
    x.x *= inv; x.y *= inv;
    *(float2*)p = x;
}

// ---------------------------------------------------------------------------
// Sequential delta-rule scan. One 128-thread block per (b,h).
// Thread layout: t = column (0..63), g = row-half (0/1, 32 rows each).
// Thread (t,g) owns S[g*32 .. g*32+31][t] in registers and mirrors it to a
// padded shared tile for the o-phase row reads.
// ---------------------------------------------------------------------------
__device__ __forceinline__ float clip1(float x) {
    return fminf(fmaxf(x, -CLAMP_F), CLAMP_F);
}

__global__ __launch_bounds__(128) void scan_kernel(float* __restrict__ state_out)
{
    __shared__ float Ssh[HEAD_DIM][HEAD_DIM + 1];
    __shared__ float ksh[HEAD_DIM];
    __shared__ float qsh[HEAD_DIM];
    __shared__ float pd[2][HEAD_DIM];    // partial v_old dots
    __shared__ float po[2][HEAD_DIM];    // partial o dots

    const int t  = threadIdx.x & 63;     // column
    const int g  = threadIdx.x >> 6;     // row half
    const int rb = g * 32;               // row base
    const int bh = blockIdx.x;           // 0..63
    const int b  = bh >> 4;
    const int h  = bh & 15;

    float Scol[32];
#pragma unroll
    for (int i = 0; i < 32; i++) { Scol[i] = 0.f; Ssh[rb + i][t] = 0.f; }

    const size_t base = (size_t)b * SEQ * HIDDEN + (size_t)h * HEAD_DIM + t;

    // prefetch step 0 (both halves load; g0 publishes k, g1 publishes q)
    float kv_n = g_k[base];
    float vv_n = g_v[base];
    float qv_n = g_q[base];
    __syncthreads();

    for (int s = 0; s < SEQ; s++) {
        const size_t idx = base + (size_t)s * HIDDEN;
        const float kv = kv_n, vv = vv_n, qv = qv_n;
        if (g == 0) ksh[t] = kv; else qsh[t] = qv;
        __syncthreads();                                   // bar1

        // prefetch next step (covers the whole step's compute)
        if (s + 1 < SEQ) {
            const size_t nidx = idx + HIDDEN;
            kv_n = g_k[nidx]; vv_n = g_v[nidx]; qv_n = g_q[nidx];
        }

        // partial v_old: sum over this half's rows of k[d]*S[d][t]
        float p0 = 0.f, p1 = 0.f, p2 = 0.f, p3 = 0.f;
#pragma unroll
        for (int i = 0; i < 32; i += 4) {
            p0 += ksh[rb + i + 0] * Scol[i + 0];
            p1 += ksh[rb + i + 1] * Scol[i + 1];
            p2 += ksh[rb + i + 2] * Scol[i + 2];
            p3 += ksh[rb + i + 3] * Scol[i + 3];
        }
        pd[g][t] = (p0 + p1) + (p2 + p3);
        __syncthreads();                                   // bar2

        const float vold  = pd[0][t] + pd[1][t];
        const float bd    = BETA_F * clip1(vv - vold);

        // update this half's rows; track local max|S|
        float lmax = 0.f;
#pragma unroll
        for (int i = 0; i < 32; i++) {
            float sdt = Scol[i] + clip1(bd * ksh[rb + i]);
            Scol[i] = sdt;
            lmax = fmaxf(lmax, fabsf(sdt));
        }
        const int over = __syncthreads_or(lmax > STATE_CAP_F);  // bar3
        if (over) {
#pragma unroll
            for (int i = 0; i < 32; i++) Scol[i] *= 0.9f;
        }
#pragma unroll
        for (int i = 0; i < 32; i++) Ssh[rb + i][t] = Scol[i];
        __syncthreads();                                   // bar4

        // o[t] partial: row t, this half's columns
        float o0 = 0.f, o1 = 0.f, o2 = 0.f, o3 = 0.f;
#pragma unroll
        for (int j = 0; j < 32; j += 4) {
            o0 += Ssh[t][rb + j + 0] * qsh[rb + j + 0];
            o1 += Ssh[t][rb + j + 1] * qsh[rb + j + 1];
            o2 += Ssh[t][rb + j + 2] * qsh[rb + j + 2];
            o3 += Ssh[t][rb + j + 3] * qsh[rb + j + 3];
        }
        po[g][t] = (o0 + o1) + (o2 + o3);
        __syncthreads();                                   // bar5

        if (g == 0)
            g_o[idx] = clip1(po[0][t] + po[1][t]);
        // bar1 of the next iteration protects ksh/qsh/Ssh rewrites
    }

    // final state: state_out[b][h][d][e]; thread (t,g) writes its 32 rows
    float* sp = state_out + (size_t)bh * HEAD_DIM * HEAD_DIM;
#pragma unroll
    for (int i = 0; i < 32; i++)
        sp[(rb + i) * HEAD_DIM + t] = Scol[i];
}

// ---------------------------------------------------------------------------
extern "C" void kernel_launch(void* const* d_in, const int* in_sizes, int n_in,
                              void* d_out, int out_size)
{
    (void)in_sizes; (void)n_in;
    const float* x  = (const float*)d_in[0];
    const float* Wq = (const float*)d_in[1];
    const float* bq = (const float*)d_in[2];
    const float* Wk = (const float*)d_in[3];
    const float* bk = (const float*)d_in[4];
    const float* Wv = (const float*)d_in[5];
    const float* bv = (const float*)d_in[6];
    const float* Wo = (const float*)d_in[7];
    const float* bo = (const float*)d_in[8];

    float* o_ptr = nullptr;
    cudaGetSymbolAddress((void**)&o_ptr, g_o);

    const int OUT_ELEMS   = ROWS * HIDDEN;                         // 4194304
    const int STATE_ELEMS = BATCH * HEADS * HEAD_DIM * HEAD_DIM;   // 262144

    float* state_out;
    if (out_size >= OUT_ELEMS + STATE_ELEMS) {
        state_out = (float*)d_out + OUT_ELEMS;
    } else {
        cudaGetSymbolAddress((void**)&state_out, g_state_scratch);
    }

    // 1) QKV projections (single launch, z selects tensor)
    dim3 gq(HIDDEN / 128, ROWS / 128, 3);
    gemm_qkv_kernel<<<gq, 256>>>(x, Wq, bq, Wk, bk, Wv, bv);

    // 2) L2 norm of q and k: 131072 head vectors, 1 warp each
    l2norm_kernel<<<(2 * ROWS * HEADS) / 8, 256>>>();

    // 3) sequential delta-rule scan, one 128-thread block per (b,h)
    scan_kernel<<<BATCH * HEADS, 128>>>(state_out);

    // 4) output projection -> d_out
    dim3 go(HIDDEN / 128, ROWS / 128);
    gemm_nt_kernel<<<go, 256>>>(o_ptr, Wo, bo, (float*)d_out,
                                HIDDEN, HIDDEN);
}